// round 1
// baseline (speedup 1.0000x reference)
#include <cuda_runtime.h>
#include <cuda_bf16.h>
#include <cstdint>

// Problem constants
#define BW_   256          // windows
#define NT_   144          // tokens per window
#define DIM_  384
#define H_    12
#define HD_   32
#define NN_   (NT_*NT_)    // 20736
#define TOW_  32
#define TABLE_ 3312
#define QKVN  1152

// ---------------- scratch (device globals: no allocation allowed) ----------------
__device__ float g_qkv[(size_t)BW_ * NT_ * QKVN];   // 170 MB
__device__ float g_att[(size_t)BW_ * NT_ * DIM_];   // 57 MB
__device__ short g_rix[8 * NN_];                    // 331 KB

// ---------------- prep: rix[gw][ij] = pi[(ij*8+gw) % NN] ----------------
__global__ void prep_rix_k(const int* __restrict__ pi, short* __restrict__ rix) {
    int idx = blockIdx.x * blockDim.x + threadIdx.x;
    if (idx >= 8 * NN_) return;
    int gw = idx / NN_;
    int ij = idx - gw * NN_;
    rix[idx] = (short)pi[(ij * 8 + gw) % NN_];
}

// ---------------- tf32 helpers ----------------
__device__ __forceinline__ unsigned f2tf(float x) {
    unsigned u;
    asm("cvt.rna.tf32.f32 %0, %1;" : "=r"(u) : "f"(x));
    return u;
}

__device__ __forceinline__ void mma_tf32(float d[4], const unsigned a[4],
                                         unsigned b0, unsigned b1) {
    asm volatile(
        "mma.sync.aligned.m16n8k8.row.col.f32.tf32.tf32.f32 "
        "{%0,%1,%2,%3},{%4,%5,%6,%7},{%8,%9},{%0,%1,%2,%3};"
        : "+f"(d[0]), "+f"(d[1]), "+f"(d[2]), "+f"(d[3])
        : "r"(a[0]), "r"(a[1]), "r"(a[2]), "r"(a[3]), "r"(b0), "r"(b1));
}

// ---------------- GEMM: C[M,N] = A[M,K] @ B[K,N] + bias[N], tf32 ----------------
// M multiple of 64, N multiple of 64, K multiple of 32. 128 threads, 64x64 tile.
__global__ void __launch_bounds__(128)
gemm_tf32_k(const float* __restrict__ A, const float* __restrict__ B,
            const float* __restrict__ bias, float* __restrict__ C,
            int N, int K) {
    __shared__ unsigned As[64][36];
    __shared__ unsigned Bs[32][72];

    const int tid  = threadIdx.x;
    const int lane = tid & 31;
    const int warp = tid >> 5;
    const int wr = (warp >> 1) * 32;   // warp row base in tile
    const int wc = (warp & 1) * 32;    // warp col base in tile
    const int g = lane >> 2;           // groupID
    const int t = lane & 3;            // thread-in-group

    const int m0 = blockIdx.y * 64;
    const int n0 = blockIdx.x * 64;

    float acc[2][4][4];
#pragma unroll
    for (int mt = 0; mt < 2; mt++)
#pragma unroll
        for (int nt = 0; nt < 4; nt++)
#pragma unroll
            for (int i = 0; i < 4; i++) acc[mt][nt][i] = 0.f;

    for (int kc = 0; kc < K; kc += 32) {
        // load A tile 64x32
#pragma unroll
        for (int p = 0; p < 4; p++) {
            int r = p * 16 + (tid >> 3);
            int c = (tid & 7) << 2;
            float4 v = *(const float4*)(A + (size_t)(m0 + r) * K + kc + c);
            As[r][c]     = f2tf(v.x);
            As[r][c + 1] = f2tf(v.y);
            As[r][c + 2] = f2tf(v.z);
            As[r][c + 3] = f2tf(v.w);
        }
        // load B tile 32x64
#pragma unroll
        for (int p = 0; p < 4; p++) {
            int r = p * 8 + (tid >> 4);
            int c = (tid & 15) << 2;
            float4 v = *(const float4*)(B + (size_t)(kc + r) * N + n0 + c);
            Bs[r][c]     = f2tf(v.x);
            Bs[r][c + 1] = f2tf(v.y);
            Bs[r][c + 2] = f2tf(v.z);
            Bs[r][c + 3] = f2tf(v.w);
        }
        __syncthreads();

#pragma unroll
        for (int ks = 0; ks < 32; ks += 8) {
            unsigned af[2][4];
#pragma unroll
            for (int mt = 0; mt < 2; mt++) {
                int rb = wr + mt * 16 + g;
                af[mt][0] = As[rb][ks + t];
                af[mt][1] = As[rb + 8][ks + t];
                af[mt][2] = As[rb][ks + t + 4];
                af[mt][3] = As[rb + 8][ks + t + 4];
            }
#pragma unroll
            for (int nt = 0; nt < 4; nt++) {
                unsigned b0 = Bs[ks + t][wc + nt * 8 + g];
                unsigned b1 = Bs[ks + t + 4][wc + nt * 8 + g];
#pragma unroll
                for (int mt = 0; mt < 2; mt++) mma_tf32(acc[mt][nt], af[mt], b0, b1);
            }
        }
        __syncthreads();
    }

    // epilogue: add bias, store
#pragma unroll
    for (int mt = 0; mt < 2; mt++) {
#pragma unroll
        for (int nt = 0; nt < 4; nt++) {
            int row = m0 + wr + mt * 16 + g;
            int col = n0 + wc + nt * 8 + (t << 1);
            float b0 = __ldg(bias + col);
            float b1 = __ldg(bias + col + 1);
            float2 lo = make_float2(acc[mt][nt][0] + b0, acc[mt][nt][1] + b1);
            float2 hi = make_float2(acc[mt][nt][2] + b0, acc[mt][nt][3] + b1);
            *(float2*)(C + (size_t)row * N + col) = lo;
            *(float2*)(C + (size_t)(row + 8) * N + col) = hi;
        }
    }
}

// ---------------- fused attention: one CTA per (head, window) ----------------
// smem layout (floats): qs[144*33] | ks[144*33] | vt[32*148] | S[144*148] | tcol[3312]
#define SST 148
#define SMEM_FLOATS (4752 + 4752 + 4736 + 21312 + 3312)
#define SMEM_BYTES  (SMEM_FLOATS * 4)

__global__ void __launch_bounds__(256, 1)
attn_k(const float* __restrict__ qkv, const float* __restrict__ mask,
       const float* __restrict__ btab, const short* __restrict__ rix,
       float* __restrict__ outp) {
    extern __shared__ float sm[];
    float* qs   = sm;                 // [144][33]
    float* kss  = sm + 4752;          // [144][33]
    float* vt   = sm + 9504;          // [32][148]  (transposed V)
    float* S    = sm + 14240;         // [144][148]
    float* tcol = sm + 35552;         // [3312]

    const int h  = blockIdx.x;
    const int bw = blockIdx.y;
    const int tid = threadIdx.x;
    const int t  = bw & 31;   // TOW index
    const int gw = bw >> 5;   // rix group
    const int w  = bw & 7;    // mask index
    const float scale = 0.17677669529663687f;  // 32^-0.5

    // ---- load q,k,v tiles ----
    const float* base = qkv + (size_t)bw * NT_ * QKVN + h * HD_;
    for (int idx = tid; idx < 1152; idx += 256) {
        int n = idx >> 3, c4 = (idx & 7) << 2;
        const float* p = base + n * QKVN + c4;
        float4 qv = *(const float4*)p;
        float4 kv = *(const float4*)(p + 384);
        float4 vv = *(const float4*)(p + 768);
        qs[n * 33 + c4]     = qv.x * scale;
        qs[n * 33 + c4 + 1] = qv.y * scale;
        qs[n * 33 + c4 + 2] = qv.z * scale;
        qs[n * 33 + c4 + 3] = qv.w * scale;
        kss[n * 33 + c4]     = kv.x;
        kss[n * 33 + c4 + 1] = kv.y;
        kss[n * 33 + c4 + 2] = kv.z;
        kss[n * 33 + c4 + 3] = kv.w;
        vt[(c4 + 0) * SST + n] = vv.x;
        vt[(c4 + 1) * SST + n] = vv.y;
        vt[(c4 + 2) * SST + n] = vv.z;
        vt[(c4 + 3) * SST + n] = vv.w;
    }
    // ---- stage bias-table column for (t, h): tcol[r] = btab[r][t][h] ----
    const float* bt = btab + t * H_ + h;
    for (int r = tid; r < TABLE_; r += 256) tcol[r] = __ldg(bt + r * (TOW_ * H_));
    __syncthreads();

    // ---- S = q @ k^T  (9x9 per thread, 16x16 threads) ----
    const int ri = (tid >> 4) * 9;
    const int cj = (tid & 15) * 9;
    float acc[9][9];
#pragma unroll
    for (int a = 0; a < 9; a++)
#pragma unroll
        for (int b = 0; b < 9; b++) acc[a][b] = 0.f;

#pragma unroll 2
    for (int d = 0; d < 32; d++) {
        float qr[9], kr[9];
#pragma unroll
        for (int a = 0; a < 9; a++) qr[a] = qs[(ri + a) * 33 + d];
#pragma unroll
        for (int b = 0; b < 9; b++) kr[b] = kss[(cj + b) * 33 + d];
#pragma unroll
        for (int a = 0; a < 9; a++)
#pragma unroll
            for (int b = 0; b < 9; b++) acc[a][b] += qr[a] * kr[b];
    }

    // ---- add bias + mask, write S to smem ----
    const short* rr = rix + gw * NN_;
    const float* mrow = mask + w * NN_;
#pragma unroll
    for (int a = 0; a < 9; a++) {
        int i = ri + a;
        int ijb = i * NT_ + cj;
#pragma unroll
        for (int b = 0; b < 9; b++) {
            int r = rr[ijb + b];
            S[i * SST + cj + b] = acc[a][b] + tcol[r] + __ldg(mrow + ijb + b);
        }
    }
    __syncthreads();

    // ---- softmax over rows (warp per row group) ----
    {
        int wid = tid >> 5, lane = tid & 31;
        for (int i = wid * 18; i < wid * 18 + 18; i++) {
            float* row = S + i * SST;
            float mx = -3.0e38f;
            for (int j = lane; j < NT_; j += 32) mx = fmaxf(mx, row[j]);
#pragma unroll
            for (int o = 16; o; o >>= 1) mx = fmaxf(mx, __shfl_xor_sync(0xffffffffu, mx, o));
            float s = 0.f;
            for (int j = lane; j < NT_; j += 32) {
                float e = __expf(row[j] - mx);
                row[j] = e;
                s += e;
            }
#pragma unroll
            for (int o = 16; o; o >>= 1) s += __shfl_xor_sync(0xffffffffu, s, o);
            float inv = 1.0f / s;
            for (int j = lane; j < NT_; j += 32) row[j] *= inv;
        }
    }
    __syncthreads();

    // ---- O = P @ V  (thread: 9 rows x 2 d-cols {d0, d0+16}) ----
    const int d0 = tid & 15;
    float o0[9], o1[9];
#pragma unroll
    for (int a = 0; a < 9; a++) { o0[a] = 0.f; o1[a] = 0.f; }

#pragma unroll 1
    for (int j = 0; j < NT_; j += 4) {
        float4 va = *(const float4*)(vt + d0 * SST + j);
        float4 vb = *(const float4*)(vt + (d0 + 16) * SST + j);
#pragma unroll
        for (int a = 0; a < 9; a++) {
            float4 p = *(const float4*)(S + (ri + a) * SST + j);
            o0[a] += p.x * va.x + p.y * va.y + p.z * va.z + p.w * va.w;
            o1[a] += p.x * vb.x + p.y * vb.y + p.z * vb.z + p.w * vb.w;
        }
    }

    // stage into qs (free now), then coalesced store: out[(bw*144+n)*384 + h*32 + d]
#pragma unroll
    for (int a = 0; a < 9; a++) {
        qs[(ri + a) * 33 + d0]      = o0[a];
        qs[(ri + a) * 33 + d0 + 16] = o1[a];
    }
    __syncthreads();

    float* orow = outp + (size_t)bw * NT_ * DIM_ + h * HD_;
    for (int idx = tid; idx < 1152; idx += 256) {
        int n = idx >> 3, c4 = (idx & 7) << 2;
        float4 v = make_float4(qs[n * 33 + c4], qs[n * 33 + c4 + 1],
                               qs[n * 33 + c4 + 2], qs[n * 33 + c4 + 3]);
        *(float4*)(orow + n * DIM_ + c4) = v;
    }
}

// ---------------- launch ----------------
extern "C" void kernel_launch(void* const* d_in, const int* in_sizes, int n_in,
                              void* d_out, int out_size) {
    const float* x        = (const float*)d_in[0];
    const float* mask     = (const float*)d_in[1];
    const float* w_qkv    = (const float*)d_in[2];
    const float* b_qkv    = (const float*)d_in[3];
    const float* w_out    = (const float*)d_in[4];
    const float* b_out    = (const float*)d_in[5];
    const float* btab     = (const float*)d_in[6];
    const int*   pos_idx  = (const int*)d_in[7];
    float* out = (float*)d_out;

    float* qkv; cudaGetSymbolAddress((void**)&qkv, g_qkv);
    float* att; cudaGetSymbolAddress((void**)&att, g_att);
    short* rix; cudaGetSymbolAddress((void**)&rix, g_rix);

    cudaFuncSetAttribute(attn_k, cudaFuncAttributeMaxDynamicSharedMemorySize, SMEM_BYTES);

    // 1. bias row-index precompute
    prep_rix_k<<<(8 * NN_ + 255) / 256, 256>>>(pos_idx, rix);

    // 2. QKV projection: (36864 x 384) @ (384 x 1152) + b
    gemm_tf32_k<<<dim3(QKVN / 64, (BW_ * NT_) / 64), 128>>>(x, w_qkv, b_qkv, qkv, QKVN, DIM_);

    // 3. fused attention per (head, window)
    attn_k<<<dim3(H_, BW_), 256, SMEM_BYTES>>>(qkv, mask, btab, rix, att);

    // 4. output projection: (36864 x 384) @ (384 x 384) + b
    gemm_tf32_k<<<dim3(DIM_ / 64, (BW_ * NT_) / 64), 128>>>(att, w_out, b_out, out, DIM_, DIM_);
}

// round 2
// speedup vs baseline: 1.8809x; 1.8809x over previous
#include <cuda_runtime.h>
#include <cuda_bf16.h>
#include <cuda_fp16.h>
#include <cstdint>

// Problem constants
#define BW_   256          // windows
#define NT_   144          // tokens per window
#define DIM_  384
#define H_    12
#define HD_   32
#define NN_   (NT_*NT_)    // 20736
#define TOW_  32
#define TABLE_ 3312
#define QKVN  1152
#define L2E   1.4426950408889634f

// ---------------- scratch (device globals: no allocation allowed) ----------------
__device__ float g_qkv[(size_t)BW_ * NT_ * QKVN];     // 170 MB
__device__ float g_att[(size_t)BW_ * NT_ * DIM_];     // 57 MB
__device__ unsigned short g_rix[8 * NN_];             // 331 KB
__device__ float g_btabT[TOW_ * H_ * TABLE_];         // 5.1 MB, [t][h][r], pre-scaled by log2e
__device__ float g_maskL[8 * NN_];                    // mask * log2e

// ---------------- prep kernels ----------------
__global__ void prep_rix_k(const int* __restrict__ pi, unsigned short* __restrict__ rix) {
    int idx = blockIdx.x * blockDim.x + threadIdx.x;
    if (idx >= 8 * NN_) return;
    int gw = idx / NN_;
    int ij = idx - gw * NN_;
    rix[idx] = (unsigned short)pi[(ij * 8 + gw) % NN_];
}

__global__ void prep_btabT_k(const float* __restrict__ btab, float* __restrict__ out) {
    int idx = blockIdx.x * blockDim.x + threadIdx.x;
    if (idx >= TOW_ * H_ * TABLE_) return;
    int th = idx / TABLE_;           // t*H + h
    int r  = idx - th * TABLE_;
    int t  = th / H_;
    int h  = th - t * H_;
    out[idx] = btab[(r * TOW_ + t) * H_ + h] * L2E;
}

__global__ void prep_maskL_k(const float* __restrict__ mask, float* __restrict__ out) {
    int idx = blockIdx.x * blockDim.x + threadIdx.x;
    if (idx >= 8 * NN_) return;
    out[idx] = mask[idx] * L2E;
}

// ---------------- math helpers ----------------
__device__ __forceinline__ unsigned f2tf(float x) {
    unsigned u;
    asm("cvt.rna.tf32.f32 %0, %1;" : "=r"(u) : "f"(x));
    return u;
}
__device__ __forceinline__ float ex2f(float x) {
    float r;
    asm("ex2.approx.ftz.f32 %0, %1;" : "=f"(r) : "f"(x));
    return r;
}
__device__ __forceinline__ unsigned packh2(float a, float b) {
    __half2 h = __floats2half2_rn(a, b);
    return *reinterpret_cast<unsigned*>(&h);
}
__device__ __forceinline__ void mma_tf32(float d[4], unsigned a0, unsigned a1,
                                         unsigned a2, unsigned a3,
                                         unsigned b0, unsigned b1) {
    asm volatile(
        "mma.sync.aligned.m16n8k8.row.col.f32.tf32.tf32.f32 "
        "{%0,%1,%2,%3},{%4,%5,%6,%7},{%8,%9},{%0,%1,%2,%3};"
        : "+f"(d[0]), "+f"(d[1]), "+f"(d[2]), "+f"(d[3])
        : "r"(a0), "r"(a1), "r"(a2), "r"(a3), "r"(b0), "r"(b1));
}
__device__ __forceinline__ void mma_f16(float d[4], unsigned a0, unsigned a1,
                                        unsigned a2, unsigned a3,
                                        unsigned b0, unsigned b1) {
    asm volatile(
        "mma.sync.aligned.m16n8k16.row.col.f32.f16.f16.f32 "
        "{%0,%1,%2,%3},{%4,%5,%6,%7},{%8,%9},{%0,%1,%2,%3};"
        : "+f"(d[0]), "+f"(d[1]), "+f"(d[2]), "+f"(d[3])
        : "r"(a0), "r"(a1), "r"(a2), "r"(a3), "r"(b0), "r"(b1));
}

// ---------------- GEMM: C[M,N] = A[M,K] @ B[K,N] + bias[N], tf32 ----------------
__global__ void __launch_bounds__(128)
gemm_tf32_k(const float* __restrict__ A, const float* __restrict__ B,
            const float* __restrict__ bias, float* __restrict__ C,
            int N, int K) {
    __shared__ unsigned As[64][36];
    __shared__ unsigned Bs[32][72];

    const int tid  = threadIdx.x;
    const int lane = tid & 31;
    const int warp = tid >> 5;
    const int wr = (warp >> 1) * 32;
    const int wc = (warp & 1) * 32;
    const int g = lane >> 2;
    const int t = lane & 3;

    const int m0 = blockIdx.y * 64;
    const int n0 = blockIdx.x * 64;

    float acc[2][4][4];
#pragma unroll
    for (int mt = 0; mt < 2; mt++)
#pragma unroll
        for (int nt = 0; nt < 4; nt++)
#pragma unroll
            for (int i = 0; i < 4; i++) acc[mt][nt][i] = 0.f;

    for (int kc = 0; kc < K; kc += 32) {
#pragma unroll
        for (int p = 0; p < 4; p++) {
            int r = p * 16 + (tid >> 3);
            int c = (tid & 7) << 2;
            float4 v = *(const float4*)(A + (size_t)(m0 + r) * K + kc + c);
            As[r][c]     = f2tf(v.x);
            As[r][c + 1] = f2tf(v.y);
            As[r][c + 2] = f2tf(v.z);
            As[r][c + 3] = f2tf(v.w);
        }
#pragma unroll
        for (int p = 0; p < 4; p++) {
            int r = p * 8 + (tid >> 4);
            int c = (tid & 15) << 2;
            float4 v = *(const float4*)(B + (size_t)(kc + r) * N + n0 + c);
            Bs[r][c]     = f2tf(v.x);
            Bs[r][c + 1] = f2tf(v.y);
            Bs[r][c + 2] = f2tf(v.z);
            Bs[r][c + 3] = f2tf(v.w);
        }
        __syncthreads();

#pragma unroll
        for (int ks = 0; ks < 32; ks += 8) {
            unsigned af[2][4];
#pragma unroll
            for (int mt = 0; mt < 2; mt++) {
                int rb = wr + mt * 16 + g;
                af[mt][0] = As[rb][ks + t];
                af[mt][1] = As[rb + 8][ks + t];
                af[mt][2] = As[rb][ks + t + 4];
                af[mt][3] = As[rb + 8][ks + t + 4];
            }
#pragma unroll
            for (int nt = 0; nt < 4; nt++) {
                unsigned b0 = Bs[ks + t][wc + nt * 8 + g];
                unsigned b1 = Bs[ks + t + 4][wc + nt * 8 + g];
#pragma unroll
                for (int mt = 0; mt < 2; mt++)
                    mma_tf32(acc[mt][nt], af[mt][0], af[mt][1], af[mt][2], af[mt][3], b0, b1);
            }
        }
        __syncthreads();
    }

#pragma unroll
    for (int mt = 0; mt < 2; mt++) {
#pragma unroll
        for (int nt = 0; nt < 4; nt++) {
            int row = m0 + wr + mt * 16 + g;
            int col = n0 + wc + nt * 8 + (t << 1);
            float b0 = __ldg(bias + col);
            float b1 = __ldg(bias + col + 1);
            float2 lo = make_float2(acc[mt][nt][0] + b0, acc[mt][nt][1] + b1);
            float2 hi = make_float2(acc[mt][nt][2] + b0, acc[mt][nt][3] + b1);
            *(float2*)(C + (size_t)row * N + col) = lo;
            *(float2*)(C + (size_t)(row + 8) * N + col) = hi;
        }
    }
}

// ---------------- fused attention: one CTA per (head, window), tensor-core ----------------
// smem (32-bit words): qs[144*36] tf32 | ks[144*36] tf32 | vh[72*40] half2 | tcol[3312] f32
#define ATT_SMEM_WORDS (5184 + 5184 + 2880 + 3312)
#define ATT_SMEM_BYTES (ATT_SMEM_WORDS * 4)

__global__ void __launch_bounds__(288, 2)
attn_k(const float* __restrict__ qkv, const float* __restrict__ maskL,
       const float* __restrict__ btabT, const unsigned short* __restrict__ rix,
       float* __restrict__ outp) {
    extern __shared__ unsigned sm[];
    unsigned* qs = sm;                       // [144][36]
    unsigned* ks = sm + 5184;                // [144][36]
    unsigned* vh = sm + 10368;               // [72][40] half2 (as u32)
    float*  tcol = (float*)(sm + 13248);     // [3312]

    const int h   = blockIdx.x;
    const int bw  = blockIdx.y;
    const int tid = threadIdx.x;
    const int lane = tid & 31;
    const int warp = tid >> 5;              // 0..8
    const int g  = lane >> 2;
    const int tq = lane & 3;
    const int r0 = warp * 16;

    const int ti = bw & 31;                 // TOW index
    const int gw = bw >> 5;                 // rix group
    const int w  = bw & 7;                  // mask index
    const float QS = 0.17677669529663687f * L2E;   // hd^-0.5 * log2e

    // ---- stage q, k (tf32) ----
    const float* base = qkv + (size_t)bw * NT_ * QKVN + h * HD_;
    for (int idx = tid; idx < 1152; idx += 288) {
        int n = idx >> 3, c4 = (idx & 7) << 2;
        const float* p = base + n * QKVN + c4;
        float4 qv = *(const float4*)p;
        float4 kv = *(const float4*)(p + 384);
        uint4 qt = make_uint4(f2tf(qv.x * QS), f2tf(qv.y * QS), f2tf(qv.z * QS), f2tf(qv.w * QS));
        uint4 kt = make_uint4(f2tf(kv.x), f2tf(kv.y), f2tf(kv.z), f2tf(kv.w));
        *(uint4*)(qs + n * 36 + c4) = qt;
        *(uint4*)(ks + n * 36 + c4) = kt;
    }
    // ---- stage V as half2 pairs along token dim: vh[jp][d] = {V[2jp][d], V[2jp+1][d]} ----
    for (int idx = tid; idx < 576; idx += 288) {
        int jp = idx >> 3, c4 = (idx & 7) << 2;
        const float* p = base + (2 * jp) * QKVN + 768 + c4;
        float4 a = *(const float4*)p;
        float4 b = *(const float4*)(p + QKVN);
        uint4 vv = make_uint4(packh2(a.x, b.x), packh2(a.y, b.y),
                              packh2(a.z, b.z), packh2(a.w, b.w));
        *(uint4*)(vh + jp * 40 + c4) = vv;
    }
    // ---- stage bias column (pre-transposed, pre-scaled) ----
    {
        const float* bt = btabT + (size_t)(ti * H_ + h) * TABLE_;
        for (int r = tid; r < TABLE_; r += 288) tcol[r] = bt[r];
    }
    __syncthreads();

    // ---- S = q @ k^T  (tf32 mma, warp: 16 rows x 144 cols) ----
    float acc[18][4];
#pragma unroll
    for (int nt = 0; nt < 18; nt++)
#pragma unroll
        for (int i = 0; i < 4; i++) acc[nt][i] = 0.f;

#pragma unroll
    for (int kk = 0; kk < 32; kk += 8) {
        unsigned a0 = qs[(r0 + g) * 36 + kk + tq];
        unsigned a1 = qs[(r0 + g + 8) * 36 + kk + tq];
        unsigned a2 = qs[(r0 + g) * 36 + kk + tq + 4];
        unsigned a3 = qs[(r0 + g + 8) * 36 + kk + tq + 4];
#pragma unroll
        for (int nt = 0; nt < 18; nt++) {
            unsigned b0 = ks[(nt * 8 + g) * 36 + kk + tq];
            unsigned b1 = ks[(nt * 8 + g) * 36 + kk + tq + 4];
            mma_tf32(acc[nt], a0, a1, a2, a3, b0, b1);
        }
    }

    // ---- bias + mask + exp2 (registers only; no max-subtraction: logits bounded) ----
    const int ia = r0 + g, ib = r0 + g + 8;
    const unsigned short* rra = rix + gw * NN_ + ia * NT_;
    const unsigned short* rrb = rix + gw * NN_ + ib * NT_;
    const float* mra = maskL + w * NN_ + ia * NT_;
    const float* mrb = maskL + w * NN_ + ib * NT_;

    float sa = 0.f, sb = 0.f;
    uint2 pf[18];
#pragma unroll
    for (int nt = 0; nt < 18; nt++) {
        int j = nt * 8 + 2 * tq;
        unsigned ra = *(const unsigned*)(rra + j);     // two u16 row indices
        unsigned rb = *(const unsigned*)(rrb + j);
        float2 ma = *(const float2*)(mra + j);
        float2 mb = *(const float2*)(mrb + j);
        float y0 = acc[nt][0] + tcol[ra & 0xFFFF] + ma.x;
        float y1 = acc[nt][1] + tcol[ra >> 16]    + ma.y;
        float y2 = acc[nt][2] + tcol[rb & 0xFFFF] + mb.x;
        float y3 = acc[nt][3] + tcol[rb >> 16]    + mb.y;
        float e0 = ex2f(y0), e1 = ex2f(y1), e2 = ex2f(y2), e3 = ex2f(y3);
        sa += e0 + e1;
        sb += e2 + e3;
        pf[nt].x = packh2(e0, e1);
        pf[nt].y = packh2(e2, e3);
    }
    // row sums live in a lane-quad (same g across tq)
    sa += __shfl_xor_sync(0xffffffffu, sa, 1);
    sa += __shfl_xor_sync(0xffffffffu, sa, 2);
    sb += __shfl_xor_sync(0xffffffffu, sb, 1);
    sb += __shfl_xor_sync(0xffffffffu, sb, 2);
    const float inva = 1.0f / sa;
    const float invb = 1.0f / sb;

    // ---- O = P @ V  (f16 mma; A fragments come straight from pf registers) ----
    float o[4][4];
#pragma unroll
    for (int nt = 0; nt < 4; nt++)
#pragma unroll
        for (int i = 0; i < 4; i++) o[nt][i] = 0.f;

#pragma unroll
    for (int kt = 0; kt < 9; kt++) {
        unsigned a0 = pf[2 * kt].x;
        unsigned a1 = pf[2 * kt].y;
        unsigned a2 = pf[2 * kt + 1].x;
        unsigned a3 = pf[2 * kt + 1].y;
#pragma unroll
        for (int nt = 0; nt < 4; nt++) {
            unsigned b0 = vh[(8 * kt + tq) * 40 + nt * 8 + g];
            unsigned b1 = vh[(8 * kt + tq + 4) * 40 + nt * 8 + g];
            mma_f16(o[nt], a0, a1, a2, a3, b0, b1);
        }
    }

    // ---- normalize + store ----
    float* orow = outp + (size_t)bw * NT_ * DIM_ + h * HD_;
#pragma unroll
    for (int nt = 0; nt < 4; nt++) {
        int col = nt * 8 + 2 * tq;
        *(float2*)(orow + ia * DIM_ + col) = make_float2(o[nt][0] * inva, o[nt][1] * inva);
        *(float2*)(orow + ib * DIM_ + col) = make_float2(o[nt][2] * invb, o[nt][3] * invb);
    }
}

// ---------------- launch ----------------
extern "C" void kernel_launch(void* const* d_in, const int* in_sizes, int n_in,
                              void* d_out, int out_size) {
    const float* x        = (const float*)d_in[0];
    const float* mask     = (const float*)d_in[1];
    const float* w_qkv    = (const float*)d_in[2];
    const float* b_qkv    = (const float*)d_in[3];
    const float* w_out    = (const float*)d_in[4];
    const float* b_out    = (const float*)d_in[5];
    const float* btab     = (const float*)d_in[6];
    const int*   pos_idx  = (const int*)d_in[7];
    float* out = (float*)d_out;

    float* qkv;   cudaGetSymbolAddress((void**)&qkv, g_qkv);
    float* att;   cudaGetSymbolAddress((void**)&att, g_att);
    unsigned short* rix; cudaGetSymbolAddress((void**)&rix, g_rix);
    float* btabT; cudaGetSymbolAddress((void**)&btabT, g_btabT);
    float* maskL; cudaGetSymbolAddress((void**)&maskL, g_maskL);

    cudaFuncSetAttribute(attn_k, cudaFuncAttributeMaxDynamicSharedMemorySize, ATT_SMEM_BYTES);

    // preprocessing
    prep_rix_k<<<(8 * NN_ + 255) / 256, 256>>>(pos_idx, rix);
    prep_btabT_k<<<(TOW_ * H_ * TABLE_ + 255) / 256, 256>>>(btab, btabT);
    prep_maskL_k<<<(8 * NN_ + 255) / 256, 256>>>(mask, maskL);

    // QKV projection: (36864 x 384) @ (384 x 1152) + b
    gemm_tf32_k<<<dim3(QKVN / 64, (BW_ * NT_) / 64), 128>>>(x, w_qkv, b_qkv, qkv, QKVN, DIM_);

    // fused attention per (head, window)
    attn_k<<<dim3(H_, BW_), 288, ATT_SMEM_BYTES>>>(qkv, maskL, btabT, rix, att);

    // output projection: (36864 x 384) @ (384 x 384) + b
    gemm_tf32_k<<<dim3(DIM_ / 64, (BW_ * NT_) / 64), 128>>>(att, w_out, b_out, out, DIM_, DIM_);
}

// round 3
// speedup vs baseline: 2.4392x; 1.2968x over previous
#include <cuda_runtime.h>
#include <cuda_bf16.h>
#include <cuda_fp16.h>
#include <cstdint>

// Problem constants
#define BW_   256          // windows
#define NT_   144          // tokens per window
#define DIM_  384
#define H_    12
#define HD_   32
#define NN_   (NT_*NT_)    // 20736
#define TOW_  32
#define TABLE_ 3312
#define QKVN  1152
#define L2E   1.4426950408889634f

// ---------------- scratch (device globals: no allocation allowed) ----------------
__device__ float g_qkv[(size_t)BW_ * NT_ * QKVN];     // 170 MB
__device__ float g_att[(size_t)BW_ * NT_ * DIM_];     // 57 MB
__device__ unsigned short g_rix[8 * NN_];             // 331 KB
__device__ float g_btabT[TOW_ * H_ * TABLE_];         // 5.1 MB, [t][h][r], pre-scaled by log2e
__device__ float g_maskL[8 * NN_];                    // mask * log2e

// ---------------- prep kernels ----------------
__global__ void prep_rix_k(const int* __restrict__ pi, unsigned short* __restrict__ rix) {
    int idx = blockIdx.x * blockDim.x + threadIdx.x;
    if (idx >= 8 * NN_) return;
    int gw = idx / NN_;
    int ij = idx - gw * NN_;
    rix[idx] = (unsigned short)pi[(ij * 8 + gw) % NN_];
}

__global__ void prep_btabT_k(const float* __restrict__ btab, float* __restrict__ out) {
    int idx = blockIdx.x * blockDim.x + threadIdx.x;
    if (idx >= TOW_ * H_ * TABLE_) return;
    int th = idx / TABLE_;           // t*H + h
    int r  = idx - th * TABLE_;
    int t  = th / H_;
    int h  = th - t * H_;
    out[idx] = btab[(r * TOW_ + t) * H_ + h] * L2E;
}

__global__ void prep_maskL_k(const float* __restrict__ mask, float* __restrict__ out) {
    int idx = blockIdx.x * blockDim.x + threadIdx.x;
    if (idx >= 8 * NN_) return;
    out[idx] = mask[idx] * L2E;
}

// ---------------- math helpers ----------------
__device__ __forceinline__ float ex2f(float x) {
    float r;
    asm("ex2.approx.ftz.f32 %0, %1;" : "=f"(r) : "f"(x));
    return r;
}
__device__ __forceinline__ unsigned packh2(float a, float b) {
    __half2 h = __floats2half2_rn(a, b);
    return *reinterpret_cast<unsigned*>(&h);
}
__device__ __forceinline__ void mma_f16(float d[4], unsigned a0, unsigned a1,
                                        unsigned a2, unsigned a3,
                                        unsigned b0, unsigned b1) {
    asm volatile(
        "mma.sync.aligned.m16n8k16.row.col.f32.f16.f16.f32 "
        "{%0,%1,%2,%3},{%4,%5,%6,%7},{%8,%9},{%0,%1,%2,%3};"
        : "+f"(d[0]), "+f"(d[1]), "+f"(d[2]), "+f"(d[3])
        : "r"(a0), "r"(a1), "r"(a2), "r"(a3), "r"(b0), "r"(b1));
}

// ---------------- GEMM: C[M,N] = A[M,K] @ B[K,N] + bias[N], fp16 mma, fp32 accum ----
// Tile 128x128xK32, 256 threads (8 warps in 4x2), double-buffered smem.
// As[buf][row][kword] : row stride 20 u32 words (16 k-pairs + pad 4)
// Bs[buf][kpair][col] : kpair stride 136 u32 words (128 cols + pad 8)
#define AS_STR 20
#define BS_STR 136
__global__ void __launch_bounds__(256)
gemm_f16_k(const float* __restrict__ A, const float* __restrict__ B,
           const float* __restrict__ bias, float* __restrict__ C,
           int N, int K) {
    __shared__ unsigned As[2][128 * AS_STR];
    __shared__ unsigned Bs[2][16 * BS_STR];

    const int tid  = threadIdx.x;
    const int lane = tid & 31;
    const int warp = tid >> 5;
    const int wm = (warp >> 1) * 32;     // warp row base
    const int wn = (warp & 1) * 64;      // warp col base
    const int g = lane >> 2;
    const int t = lane & 3;

    const int m0 = blockIdx.y * 128;
    const int n0 = blockIdx.x * 128;
    const int niter = K / 32;

    float acc[2][8][4];
#pragma unroll
    for (int mt = 0; mt < 2; mt++)
#pragma unroll
        for (int nt = 0; nt < 8; nt++)
#pragma unroll
            for (int i = 0; i < 4; i++) acc[mt][nt][i] = 0.f;

    // per-thread load coordinates
    // A: 4 pieces, idx = tid + p*256; r = idx>>3 (0..127), c4 = (idx&7)*4
    // B: 2 pieces, idx = tid + p*256; kp = idx>>5 (0..15), c4 = (idx&31)*4
    float4 ar[4], br0[2], br1[2];

    // prologue: load chunk 0
#pragma unroll
    for (int p = 0; p < 4; p++) {
        int idx = tid + p * 256;
        int r = idx >> 3, c4 = (idx & 7) << 2;
        ar[p] = *(const float4*)(A + (size_t)(m0 + r) * K + c4);
    }
#pragma unroll
    for (int p = 0; p < 2; p++) {
        int idx = tid + p * 256;
        int kp = idx >> 5, c4 = (idx & 31) << 2;
        br0[p] = *(const float4*)(B + (size_t)(2 * kp) * N + n0 + c4);
        br1[p] = *(const float4*)(B + (size_t)(2 * kp + 1) * N + n0 + c4);
    }
#pragma unroll
    for (int p = 0; p < 4; p++) {
        int idx = tid + p * 256;
        int r = idx >> 3, w2 = (idx & 7) << 1;
        *(uint2*)&As[0][r * AS_STR + w2] =
            make_uint2(packh2(ar[p].x, ar[p].y), packh2(ar[p].z, ar[p].w));
    }
#pragma unroll
    for (int p = 0; p < 2; p++) {
        int idx = tid + p * 256;
        int kp = idx >> 5, c4 = (idx & 31) << 2;
        *(uint4*)&Bs[0][kp * BS_STR + c4] =
            make_uint4(packh2(br0[p].x, br1[p].x), packh2(br0[p].y, br1[p].y),
                       packh2(br0[p].z, br1[p].z), packh2(br0[p].w, br1[p].w));
    }
    __syncthreads();

    for (int it = 0; it < niter; it++) {
        const int buf = it & 1;
        const int kc = (it + 1) * 32;
        if (it + 1 < niter) {
            // prefetch next chunk into registers
#pragma unroll
            for (int p = 0; p < 4; p++) {
                int idx = tid + p * 256;
                int r = idx >> 3, c4 = (idx & 7) << 2;
                ar[p] = *(const float4*)(A + (size_t)(m0 + r) * K + kc + c4);
            }
#pragma unroll
            for (int p = 0; p < 2; p++) {
                int idx = tid + p * 256;
                int kp = idx >> 5, c4 = (idx & 31) << 2;
                br0[p] = *(const float4*)(B + (size_t)(kc + 2 * kp) * N + n0 + c4);
                br1[p] = *(const float4*)(B + (size_t)(kc + 2 * kp + 1) * N + n0 + c4);
            }
        }

        // compute on smem[buf]
        const unsigned* as = As[buf];
        const unsigned* bs = Bs[buf];
#pragma unroll
        for (int ks = 0; ks < 2; ks++) {
            unsigned af[2][4];
#pragma unroll
            for (int mt = 0; mt < 2; mt++) {
                int ra = wm + mt * 16 + g;
                af[mt][0] = as[ra * AS_STR + ks * 8 + t];
                af[mt][1] = as[(ra + 8) * AS_STR + ks * 8 + t];
                af[mt][2] = as[ra * AS_STR + ks * 8 + t + 4];
                af[mt][3] = as[(ra + 8) * AS_STR + ks * 8 + t + 4];
            }
#pragma unroll
            for (int nt = 0; nt < 8; nt++) {
                int col = wn + nt * 8 + g;
                unsigned b0 = bs[(ks * 8 + t) * BS_STR + col];
                unsigned b1 = bs[(ks * 8 + t + 4) * BS_STR + col];
#pragma unroll
                for (int mt = 0; mt < 2; mt++)
                    mma_f16(acc[mt][nt], af[mt][0], af[mt][1], af[mt][2], af[mt][3], b0, b1);
            }
        }

        if (it + 1 < niter) {
            // store next chunk into the other buffer (safe: that buffer's data
            // was consumed in iteration it-1, sync at end of it-1 guarantees it)
#pragma unroll
            for (int p = 0; p < 4; p++) {
                int idx = tid + p * 256;
                int r = idx >> 3, w2 = (idx & 7) << 1;
                *(uint2*)&As[buf ^ 1][r * AS_STR + w2] =
                    make_uint2(packh2(ar[p].x, ar[p].y), packh2(ar[p].z, ar[p].w));
            }
#pragma unroll
            for (int p = 0; p < 2; p++) {
                int idx = tid + p * 256;
                int kp = idx >> 5, c4 = (idx & 31) << 2;
                *(uint4*)&Bs[buf ^ 1][kp * BS_STR + c4] =
                    make_uint4(packh2(br0[p].x, br1[p].x), packh2(br0[p].y, br1[p].y),
                               packh2(br0[p].z, br1[p].z), packh2(br0[p].w, br1[p].w));
            }
            __syncthreads();
        }
    }

    // epilogue: add bias, store
#pragma unroll
    for (int mt = 0; mt < 2; mt++) {
#pragma unroll
        for (int nt = 0; nt < 8; nt++) {
            int row = m0 + wm + mt * 16 + g;
            int col = n0 + wn + nt * 8 + (t << 1);
            float b0 = __ldg(bias + col);
            float b1 = __ldg(bias + col + 1);
            float2 lo = make_float2(acc[mt][nt][0] + b0, acc[mt][nt][1] + b1);
            float2 hi = make_float2(acc[mt][nt][2] + b0, acc[mt][nt][3] + b1);
            *(float2*)(C + (size_t)row * N + col) = lo;
            *(float2*)(C + (size_t)(row + 8) * N + col) = hi;
        }
    }
}

// ---------------- fused attention: one CTA per (head, window), fp16 tensor-core ----
// smem (u32 words): qh[144*20] | kh[144*20] | vh[72*40] | tcol[3312]
#define QK_STR 20
#define ATT_SMEM_WORDS (2880 + 2880 + 2880 + 3312)
#define ATT_SMEM_BYTES (ATT_SMEM_WORDS * 4)

__global__ void __launch_bounds__(288, 2)
attn_k(const float* __restrict__ qkv, const float* __restrict__ maskL,
       const float* __restrict__ btabT, const unsigned short* __restrict__ rix,
       float* __restrict__ outp) {
    extern __shared__ unsigned sm[];
    unsigned* qh = sm;                       // [144][20] half2 pairs along d
    unsigned* kh = sm + 2880;                // [144][20]
    unsigned* vh = sm + 5760;                // [72][40] half2 pairs along token
    float*  tcol = (float*)(sm + 8640);      // [3312]

    const int h   = blockIdx.x;
    const int bw  = blockIdx.y;
    const int tid = threadIdx.x;
    const int lane = tid & 31;
    const int warp = tid >> 5;              // 0..8
    const int g  = lane >> 2;
    const int tq = lane & 3;
    const int r0 = warp * 16;

    const int ti = bw & 31;                 // TOW index
    const int gw = bw >> 5;                 // rix group
    const int w  = bw & 7;                  // mask index
    const float QS = 0.17677669529663687f * L2E;   // hd^-0.5 * log2e

    // ---- stage q, k as half2 pairs along d ----
    const float* base = qkv + (size_t)bw * NT_ * QKVN + h * HD_;
    for (int idx = tid; idx < 1152; idx += 288) {
        int n = idx >> 3, c4 = (idx & 7) << 2;
        const float* p = base + n * QKVN + c4;
        float4 qv = *(const float4*)p;
        float4 kv = *(const float4*)(p + 384);
        *(uint2*)(qh + n * QK_STR + (c4 >> 1)) =
            make_uint2(packh2(qv.x * QS, qv.y * QS), packh2(qv.z * QS, qv.w * QS));
        *(uint2*)(kh + n * QK_STR + (c4 >> 1)) =
            make_uint2(packh2(kv.x, kv.y), packh2(kv.z, kv.w));
    }
    // ---- stage V as half2 pairs along token dim ----
    for (int idx = tid; idx < 576; idx += 288) {
        int jp = idx >> 3, c4 = (idx & 7) << 2;
        const float* p = base + (2 * jp) * QKVN + 768 + c4;
        float4 a = *(const float4*)p;
        float4 b = *(const float4*)(p + QKVN);
        *(uint4*)(vh + jp * 40 + c4) = make_uint4(packh2(a.x, b.x), packh2(a.y, b.y),
                                                  packh2(a.z, b.z), packh2(a.w, b.w));
    }
    // ---- stage bias column (pre-transposed, pre-scaled) ----
    {
        const float* bt = btabT + (size_t)(ti * H_ + h) * TABLE_;
        for (int r = tid; r < TABLE_; r += 288) tcol[r] = bt[r];
    }
    __syncthreads();

    // ---- S = q @ k^T  (f16 mma k16, warp: 16 rows x 144 cols) ----
    float acc[18][4];
#pragma unroll
    for (int nt = 0; nt < 18; nt++)
#pragma unroll
        for (int i = 0; i < 4; i++) acc[nt][i] = 0.f;

#pragma unroll
    for (int ks = 0; ks < 2; ks++) {
        unsigned a0 = qh[(r0 + g) * QK_STR + ks * 8 + tq];
        unsigned a1 = qh[(r0 + g + 8) * QK_STR + ks * 8 + tq];
        unsigned a2 = qh[(r0 + g) * QK_STR + ks * 8 + tq + 4];
        unsigned a3 = qh[(r0 + g + 8) * QK_STR + ks * 8 + tq + 4];
#pragma unroll
        for (int nt = 0; nt < 18; nt++) {
            unsigned b0 = kh[(nt * 8 + g) * QK_STR + ks * 8 + tq];
            unsigned b1 = kh[(nt * 8 + g) * QK_STR + ks * 8 + tq + 4];
            mma_f16(acc[nt], a0, a1, a2, a3, b0, b1);
        }
    }

    // ---- bias + mask + exp2 (registers only) ----
    const int ia = r0 + g, ib = r0 + g + 8;
    const unsigned short* rra = rix + gw * NN_ + ia * NT_;
    const unsigned short* rrb = rix + gw * NN_ + ib * NT_;
    const float* mra = maskL + w * NN_ + ia * NT_;
    const float* mrb = maskL + w * NN_ + ib * NT_;

    float sa = 0.f, sb = 0.f;
    uint2 pf[18];
#pragma unroll
    for (int nt = 0; nt < 18; nt++) {
        int j = nt * 8 + 2 * tq;
        unsigned ra = *(const unsigned*)(rra + j);
        unsigned rb = *(const unsigned*)(rrb + j);
        float2 ma = *(const float2*)(mra + j);
        float2 mb = *(const float2*)(mrb + j);
        float y0 = acc[nt][0] + tcol[ra & 0xFFFF] + ma.x;
        float y1 = acc[nt][1] + tcol[ra >> 16]    + ma.y;
        float y2 = acc[nt][2] + tcol[rb & 0xFFFF] + mb.x;
        float y3 = acc[nt][3] + tcol[rb >> 16]    + mb.y;
        float e0 = ex2f(y0), e1 = ex2f(y1), e2 = ex2f(y2), e3 = ex2f(y3);
        sa += e0 + e1;
        sb += e2 + e3;
        pf[nt].x = packh2(e0, e1);
        pf[nt].y = packh2(e2, e3);
    }
    sa += __shfl_xor_sync(0xffffffffu, sa, 1);
    sa += __shfl_xor_sync(0xffffffffu, sa, 2);
    sb += __shfl_xor_sync(0xffffffffu, sb, 1);
    sb += __shfl_xor_sync(0xffffffffu, sb, 2);
    const float inva = 1.0f / sa;
    const float invb = 1.0f / sb;

    // ---- O = P @ V  (f16 mma; A fragments straight from pf registers) ----
    float o[4][4];
#pragma unroll
    for (int nt = 0; nt < 4; nt++)
#pragma unroll
        for (int i = 0; i < 4; i++) o[nt][i] = 0.f;

#pragma unroll
    for (int kt = 0; kt < 9; kt++) {
        unsigned a0 = pf[2 * kt].x;
        unsigned a1 = pf[2 * kt].y;
        unsigned a2 = pf[2 * kt + 1].x;
        unsigned a3 = pf[2 * kt + 1].y;
#pragma unroll
        for (int nt = 0; nt < 4; nt++) {
            unsigned b0 = vh[(8 * kt + tq) * 40 + nt * 8 + g];
            unsigned b1 = vh[(8 * kt + tq + 4) * 40 + nt * 8 + g];
            mma_f16(o[nt], a0, a1, a2, a3, b0, b1);
        }
    }

    // ---- normalize + store ----
    float* orow = outp + (size_t)bw * NT_ * DIM_ + h * HD_;
#pragma unroll
    for (int nt = 0; nt < 4; nt++) {
        int col = nt * 8 + 2 * tq;
        *(float2*)(orow + ia * DIM_ + col) = make_float2(o[nt][0] * inva, o[nt][1] * inva);
        *(float2*)(orow + ib * DIM_ + col) = make_float2(o[nt][2] * invb, o[nt][3] * invb);
    }
}

// ---------------- launch ----------------
extern "C" void kernel_launch(void* const* d_in, const int* in_sizes, int n_in,
                              void* d_out, int out_size) {
    const float* x        = (const float*)d_in[0];
    const float* mask     = (const float*)d_in[1];
    const float* w_qkv    = (const float*)d_in[2];
    const float* b_qkv    = (const float*)d_in[3];
    const float* w_out    = (const float*)d_in[4];
    const float* b_out    = (const float*)d_in[5];
    const float* btab     = (const float*)d_in[6];
    const int*   pos_idx  = (const int*)d_in[7];
    float* out = (float*)d_out;

    float* qkv;   cudaGetSymbolAddress((void**)&qkv, g_qkv);
    float* att;   cudaGetSymbolAddress((void**)&att, g_att);
    unsigned short* rix; cudaGetSymbolAddress((void**)&rix, g_rix);
    float* btabT; cudaGetSymbolAddress((void**)&btabT, g_btabT);
    float* maskL; cudaGetSymbolAddress((void**)&maskL, g_maskL);

    cudaFuncSetAttribute(attn_k, cudaFuncAttributeMaxDynamicSharedMemorySize, ATT_SMEM_BYTES);

    // preprocessing
    prep_rix_k<<<(8 * NN_ + 255) / 256, 256>>>(pos_idx, rix);
    prep_btabT_k<<<(TOW_ * H_ * TABLE_ + 255) / 256, 256>>>(btab, btabT);
    prep_maskL_k<<<(8 * NN_ + 255) / 256, 256>>>(mask, maskL);

    // QKV projection: (36864 x 384) @ (384 x 1152) + b
    gemm_f16_k<<<dim3(QKVN / 128, (BW_ * NT_) / 128), 256>>>(x, w_qkv, b_qkv, qkv, QKVN, DIM_);

    // fused attention per (head, window)
    attn_k<<<dim3(H_, BW_), 288, ATT_SMEM_BYTES>>>(qkv, maskL, btabT, rix, att);

    // output projection: (36864 x 384) @ (384 x 384) + b
    gemm_f16_k<<<dim3(DIM_ / 128, (BW_ * NT_) / 128), 256>>>(att, w_out, b_out, out, DIM_, DIM_);
}

// round 6
// speedup vs baseline: 3.4105x; 1.3982x over previous
#include <cuda_runtime.h>
#include <cuda_bf16.h>
#include <cuda_fp16.h>
#include <cstdint>

// Problem constants
#define BW_   256
#define NT_   144
#define DIM_  384
#define H_    12
#define HD_   32
#define NN_   (NT_*NT_)    // 20736
#define TOW_  32
#define TABLE_ 3312
#define QKVN  1152
#define L2E   1.4426950408889634f
#define QS_   (0.17677669529663687f * L2E)

// ---------------- scratch ----------------
__device__ __half g_xh[(size_t)BW_ * NT_ * DIM_];        // 28 MB
__device__ __half g_qkvh[(size_t)BW_ * NT_ * QKVN];      // 85 MB
__device__ __half g_atth[(size_t)BW_ * NT_ * DIM_];      // 28 MB
__device__ unsigned g_wqp[(DIM_/2) * QKVN];              // kp-paired w_qkv (q-scaled)
__device__ unsigned g_wop[(DIM_/2) * DIM_];              // kp-paired w_out
__device__ float g_bqs[QKVN];                            // scaled qkv bias
__device__ unsigned short g_rix[8 * NN_];
__device__ float g_btabT[TOW_ * H_ * TABLE_];            // [t][h][r] * log2e
__device__ float g_maskL[8 * NN_];                       // mask * log2e

// ---------------- prep kernels ----------------
__global__ void conv_x_k(const float* __restrict__ x, __half* __restrict__ xh, int n4) {
    int i = blockIdx.x * blockDim.x + threadIdx.x;
    if (i >= n4) return;
    float4 v = *(const float4*)(x + 4 * (size_t)i);
    __half2 a = __floats2half2_rn(v.x, v.y);
    __half2 b = __floats2half2_rn(v.z, v.w);
    *(uint2*)(xh + 4 * (size_t)i) = make_uint2(*(unsigned*)&a, *(unsigned*)&b);
}

__global__ void pack_wq_k(const float* __restrict__ w, unsigned* __restrict__ wp) {
    int i = blockIdx.x * blockDim.x + threadIdx.x;      // kp*1152 + n
    if (i >= (DIM_/2) * QKVN) return;
    int kp = i / QKVN, n = i - kp * QKVN;
    float s = (n < DIM_) ? QS_ : 1.0f;
    __half2 h = __floats2half2_rn(w[(size_t)(2*kp) * QKVN + n] * s,
                                  w[(size_t)(2*kp+1) * QKVN + n] * s);
    wp[i] = *(unsigned*)&h;
}

__global__ void pack_wo_k(const float* __restrict__ w, unsigned* __restrict__ wp) {
    int i = blockIdx.x * blockDim.x + threadIdx.x;
    if (i >= (DIM_/2) * DIM_) return;
    int kp = i / DIM_, n = i - kp * DIM_;
    __half2 h = __floats2half2_rn(w[(size_t)(2*kp) * DIM_ + n],
                                  w[(size_t)(2*kp+1) * DIM_ + n]);
    wp[i] = *(unsigned*)&h;
}

__global__ void prep_bq_k(const float* __restrict__ b, float* __restrict__ o) {
    int i = blockIdx.x * blockDim.x + threadIdx.x;
    if (i >= QKVN) return;
    o[i] = b[i] * ((i < DIM_) ? QS_ : 1.0f);
}

__global__ void prep_rix_k(const int* __restrict__ pi, unsigned short* __restrict__ rix) {
    int idx = blockIdx.x * blockDim.x + threadIdx.x;
    if (idx >= 8 * NN_) return;
    int gw = idx / NN_;
    int ij = idx - gw * NN_;
    rix[idx] = (unsigned short)pi[(ij * 8 + gw) % NN_];
}

__global__ void prep_btabT_k(const float* __restrict__ btab, float* __restrict__ out) {
    int idx = blockIdx.x * blockDim.x + threadIdx.x;
    if (idx >= TOW_ * H_ * TABLE_) return;
    int th = idx / TABLE_;
    int r  = idx - th * TABLE_;
    int t  = th / H_;
    int h  = th - t * H_;
    out[idx] = btab[(r * TOW_ + t) * H_ + h] * L2E;
}

__global__ void prep_maskL_k(const float* __restrict__ mask, float* __restrict__ out) {
    int idx = blockIdx.x * blockDim.x + threadIdx.x;
    if (idx >= 8 * NN_) return;
    out[idx] = mask[idx] * L2E;
}

// ---------------- math helpers ----------------
__device__ __forceinline__ float ex2f(float x) {
    float r; asm("ex2.approx.ftz.f32 %0, %1;" : "=f"(r) : "f"(x)); return r;
}
__device__ __forceinline__ unsigned packh2(float a, float b) {
    __half2 h = __floats2half2_rn(a, b);
    return *reinterpret_cast<unsigned*>(&h);
}
__device__ __forceinline__ void mma_f16(float d[4], unsigned a0, unsigned a1,
                                        unsigned a2, unsigned a3,
                                        unsigned b0, unsigned b1) {
    asm volatile(
        "mma.sync.aligned.m16n8k16.row.col.f32.f16.f16.f32 "
        "{%0,%1,%2,%3},{%4,%5,%6,%7},{%8,%9},{%0,%1,%2,%3};"
        : "+f"(d[0]), "+f"(d[1]), "+f"(d[2]), "+f"(d[3])
        : "r"(a0), "r"(a1), "r"(a2), "r"(a3), "r"(b0), "r"(b1));
}
__device__ __forceinline__ void cpa16(unsigned dst, const void* src) {
    asm volatile("cp.async.cg.shared.global [%0], [%1], 16;" :: "r"(dst), "l"(src));
}
#define CPA_COMMIT() asm volatile("cp.async.commit_group;")
#define CPA_WAIT1()  asm volatile("cp.async.wait_group 1;")
#define CPA_WAIT0()  asm volatile("cp.async.wait_group 0;")

// ---------------- GEMM: C = A(half,[M][K]) @ W(kp-paired u32,[K/2][N]) + bias ----
// Tile 128x128, KC=64, 256 threads, 3-stage cp.async pipeline.
// As[stage][row][word(32)] swizzle: chunk ^ (row&7) at 16B granularity
// Bs[stage][kp][word(128)] swizzle: word ^ (8*(kp&3))
#define GSM_BYTES (3 * (16384 + 16384))
template<bool HALF_OUT>
__global__ void __launch_bounds__(256, 2)
gemm_cp_k(const __half* __restrict__ A, const unsigned* __restrict__ Bp,
          const float* __restrict__ bias, void* __restrict__ Cv,
          int N, int K) {
    extern __shared__ unsigned smg[];
    unsigned* As = smg;              // [3][4096]
    unsigned* Bs = smg + 3 * 4096;   // [3][4096]
    const unsigned sa_base = (unsigned)__cvta_generic_to_shared(As);
    const unsigned sb_base = (unsigned)__cvta_generic_to_shared(Bs);

    const int tid  = threadIdx.x;
    const int lane = tid & 31;
    const int warp = tid >> 5;
    const int wm = (warp >> 1) * 32;
    const int wn = (warp & 1) * 64;
    const int g = lane >> 2;
    const int t = lane & 3;

    const int m0 = blockIdx.y * 128;
    const int n0 = blockIdx.x * 128;
    const int nch = K / 64;

    float acc[2][8][4];
#pragma unroll
    for (int mt = 0; mt < 2; mt++)
#pragma unroll
        for (int nt = 0; nt < 8; nt++)
#pragma unroll
            for (int i = 0; i < 4; i++) acc[mt][nt][i] = 0.f;

    // B fragment column index (swizzle folded: (wn+nt*8)^(8t) + g)
    int bcol[8];
#pragma unroll
    for (int nt = 0; nt < 8; nt++) bcol[nt] = ((wn + nt * 8) ^ (t << 3)) + g;

#define GEMM_ISSUE(stage, ch) do {                                              \
        int kc_ = (ch) * 64;                                                    \
        unsigned ab_ = sa_base + (stage) * 16384;                               \
        unsigned bb_ = sb_base + (stage) * 16384;                               \
        _Pragma("unroll")                                                       \
        for (int p = 0; p < 4; p++) {                                           \
            int idx = tid + p * 256;                                            \
            int r = idx >> 3, g4 = idx & 7;                                     \
            unsigned dst = ab_ + (r * 32 + 4 * (g4 ^ (r & 7))) * 4;             \
            cpa16(dst, A + (size_t)(m0 + r) * K + kc_ + g4 * 8);                \
        }                                                                       \
        _Pragma("unroll")                                                       \
        for (int p = 0; p < 4; p++) {                                           \
            int idx = tid + p * 256;                                            \
            int kp = idx >> 5, g4 = idx & 31;                                   \
            unsigned dst = bb_ + (kp * 128 + 4 * (g4 ^ (2 * (kp & 3)))) * 4;    \
            cpa16(dst, Bp + (size_t)(kc_ / 2 + kp) * N + n0 + g4 * 4);          \
        }                                                                       \
    } while (0)

    GEMM_ISSUE(0, 0); CPA_COMMIT();
    GEMM_ISSUE(1, 1); CPA_COMMIT();

    for (int it = 0; it < nch; it++) {
        // TAIL FIX: on the last chunk no new group was committed after it, so
        // wait_group 1 could leave THIS chunk's copy pending. Drain fully.
        if (it + 1 == nch) { CPA_WAIT0(); } else { CPA_WAIT1(); }
        __syncthreads();
        if (it + 2 < nch) { GEMM_ISSUE((it + 2) % 3, it + 2); CPA_COMMIT(); }

        const unsigned* as = As + (it % 3) * 4096;
        const unsigned* bs = Bs + (it % 3) * 4096;
#pragma unroll
        for (int ks = 0; ks < 4; ks++) {
            const int w0 = (8 * ks + t) ^ (g << 2);
            const int w1 = (8 * ks + 4 + t) ^ (g << 2);
            unsigned af[2][4];
#pragma unroll
            for (int mt = 0; mt < 2; mt++) {
                const unsigned* ra = as + (wm + mt * 16 + g) * 32;
                af[mt][0] = ra[w0];
                af[mt][1] = ra[8 * 32 + w0];
                af[mt][2] = ra[w1];
                af[mt][3] = ra[8 * 32 + w1];
            }
            const unsigned* b0r = bs + (8 * ks + t) * 128;
            const unsigned* b1r = bs + (8 * ks + 4 + t) * 128;
#pragma unroll
            for (int nt = 0; nt < 8; nt++) {
                unsigned b0 = b0r[bcol[nt]];
                unsigned b1 = b1r[bcol[nt]];
#pragma unroll
                for (int mt = 0; mt < 2; mt++)
                    mma_f16(acc[mt][nt], af[mt][0], af[mt][1], af[mt][2], af[mt][3], b0, b1);
            }
        }
    }

    // epilogue
#pragma unroll
    for (int mt = 0; mt < 2; mt++) {
#pragma unroll
        for (int nt = 0; nt < 8; nt++) {
            int row = m0 + wm + mt * 16 + g;
            int col = n0 + wn + nt * 8 + (t << 1);
            float b0 = __ldg(bias + col);
            float b1 = __ldg(bias + col + 1);
            float v0 = acc[mt][nt][0] + b0, v1 = acc[mt][nt][1] + b1;
            float v2 = acc[mt][nt][2] + b0, v3 = acc[mt][nt][3] + b1;
            if (HALF_OUT) {
                unsigned* C = (unsigned*)Cv;
                C[(size_t)row * (N >> 1) + (col >> 1)] = packh2(v0, v1);
                C[(size_t)(row + 8) * (N >> 1) + (col >> 1)] = packh2(v2, v3);
            } else {
                float* C = (float*)Cv;
                *(float2*)(C + (size_t)row * N + col) = make_float2(v0, v1);
                *(float2*)(C + (size_t)(row + 8) * N + col) = make_float2(v2, v3);
            }
        }
    }
#undef GEMM_ISSUE
}

// ---------------- fused attention: one CTA per (head, window) ----------------
// smem (u32): qh[144*36] | kh[144*36] | vh[72*40] | tcol[3312]
#define QK_STR 36
#define ATT_SMEM_WORDS (5184 + 5184 + 2880 + 3312)
#define ATT_SMEM_BYTES (ATT_SMEM_WORDS * 4)

__global__ void __launch_bounds__(288, 2)
attn_k(const __half* __restrict__ qkvh, const float* __restrict__ maskL,
       const float* __restrict__ btabT, const unsigned short* __restrict__ rix,
       __half* __restrict__ atth) {
    extern __shared__ unsigned sm[];
    unsigned* qh = sm;                       // [144][36]
    unsigned* kh = sm + 5184;                // [144][36]
    unsigned* vh = sm + 10368;               // [72][40]
    float*  tcol = (float*)(sm + 13248);     // [3312]

    const int h   = blockIdx.x;
    const int bw  = blockIdx.y;
    const int tid = threadIdx.x;
    const int lane = tid & 31;
    const int warp = tid >> 5;               // 0..8
    const int g  = lane >> 2;
    const int tq = lane & 3;
    const int r0 = warp * 16;

    const int ti = bw & 31;
    const int gw = bw >> 5;
    const int w  = bw & 7;

    // qkv row = 1152 halves = 576 u32; q at u32 offset h*16, k +192, v +384
    const unsigned* bu = (const unsigned*)qkvh + (size_t)bw * NT_ * 576 + h * 16;

    // ---- stage q,k (pure copies; q pre-scaled in weights) ----
    for (int idx = tid; idx < 576; idx += 288) {
        int n = idx >> 2, s = (idx & 3) << 2;
        const unsigned* p = bu + (size_t)n * 576 + s;
        *(uint4*)(qh + n * QK_STR + s) = *(const uint4*)p;
        *(uint4*)(kh + n * QK_STR + s) = *(const uint4*)(p + 192);
    }
    // ---- stage V paired along tokens: vh[jp][d] = {V[2jp][d], V[2jp+1][d]} ----
    for (int idx = tid; idx < 576; idx += 288) {
        int jp = idx >> 3, s = idx & 7;
        const unsigned* p0 = bu + (size_t)(2 * jp) * 576 + 384 + s * 2;
        uint2 u = *(const uint2*)p0;
        uint2 v = *(const uint2*)(p0 + 576);
        uint4 o;
        o.x = __byte_perm(u.x, v.x, 0x5410);
        o.y = __byte_perm(u.x, v.x, 0x7632);
        o.z = __byte_perm(u.y, v.y, 0x5410);
        o.w = __byte_perm(u.y, v.y, 0x7632);
        *(uint4*)(vh + jp * 40 + s * 4) = o;
    }
    // ---- stage bias column ----
    {
        const float* bt = btabT + (size_t)(ti * H_ + h) * TABLE_;
        for (int r = tid; r < TABLE_; r += 288) tcol[r] = bt[r];
    }
    __syncthreads();

    // ---- S = q @ k^T ----
    float acc[18][4];
#pragma unroll
    for (int nt = 0; nt < 18; nt++)
#pragma unroll
        for (int i = 0; i < 4; i++) acc[nt][i] = 0.f;

#pragma unroll
    for (int ks = 0; ks < 2; ks++) {
        unsigned a0 = qh[(r0 + g) * QK_STR + ks * 8 + tq];
        unsigned a1 = qh[(r0 + g + 8) * QK_STR + ks * 8 + tq];
        unsigned a2 = qh[(r0 + g) * QK_STR + ks * 8 + tq + 4];
        unsigned a3 = qh[(r0 + g + 8) * QK_STR + ks * 8 + tq + 4];
#pragma unroll
        for (int nt = 0; nt < 18; nt++) {
            unsigned b0 = kh[(nt * 8 + g) * QK_STR + ks * 8 + tq];
            unsigned b1 = kh[(nt * 8 + g) * QK_STR + ks * 8 + tq + 4];
            mma_f16(acc[nt], a0, a1, a2, a3, b0, b1);
        }
    }

    // ---- bias + mask + exp2 ----
    const int ia = r0 + g, ib = r0 + g + 8;
    const unsigned short* rra = rix + gw * NN_ + ia * NT_;
    const unsigned short* rrb = rix + gw * NN_ + ib * NT_;
    const float* mra = maskL + w * NN_ + ia * NT_;
    const float* mrb = maskL + w * NN_ + ib * NT_;

    float sa = 0.f, sb = 0.f;
    uint2 pf[18];
#pragma unroll
    for (int nt = 0; nt < 18; nt++) {
        int j = nt * 8 + 2 * tq;
        unsigned ra = *(const unsigned*)(rra + j);
        unsigned rb = *(const unsigned*)(rrb + j);
        float2 ma = *(const float2*)(mra + j);
        float2 mb = *(const float2*)(mrb + j);
        float y0 = acc[nt][0] + tcol[ra & 0xFFFF] + ma.x;
        float y1 = acc[nt][1] + tcol[ra >> 16]    + ma.y;
        float y2 = acc[nt][2] + tcol[rb & 0xFFFF] + mb.x;
        float y3 = acc[nt][3] + tcol[rb >> 16]    + mb.y;
        float e0 = ex2f(y0), e1 = ex2f(y1), e2 = ex2f(y2), e3 = ex2f(y3);
        sa += e0 + e1;
        sb += e2 + e3;
        pf[nt].x = packh2(e0, e1);
        pf[nt].y = packh2(e2, e3);
    }
    sa += __shfl_xor_sync(0xffffffffu, sa, 1);
    sa += __shfl_xor_sync(0xffffffffu, sa, 2);
    sb += __shfl_xor_sync(0xffffffffu, sb, 1);
    sb += __shfl_xor_sync(0xffffffffu, sb, 2);
    const float inva = 1.0f / sa;
    const float invb = 1.0f / sb;

    // ---- O = P @ V ----
    float o[4][4];
#pragma unroll
    for (int nt = 0; nt < 4; nt++)
#pragma unroll
        for (int i = 0; i < 4; i++) o[nt][i] = 0.f;

#pragma unroll
    for (int kt = 0; kt < 9; kt++) {
        unsigned a0 = pf[2 * kt].x;
        unsigned a1 = pf[2 * kt].y;
        unsigned a2 = pf[2 * kt + 1].x;
        unsigned a3 = pf[2 * kt + 1].y;
#pragma unroll
        for (int nt = 0; nt < 4; nt++) {
            unsigned b0 = vh[(8 * kt + tq) * 40 + nt * 8 + g];
            unsigned b1 = vh[(8 * kt + tq + 4) * 40 + nt * 8 + g];
            mma_f16(o[nt], a0, a1, a2, a3, b0, b1);
        }
    }

    // ---- normalize + store half ----
    unsigned* orow = (unsigned*)atth + (size_t)bw * NT_ * 192 + h * 16;
#pragma unroll
    for (int nt = 0; nt < 4; nt++) {
        int cw = nt * 4 + tq;   // u32 col within head (pairs 2tq,2tq+1)
        orow[(size_t)ia * 192 + cw] = packh2(o[nt][0] * inva, o[nt][1] * inva);
        orow[(size_t)ib * 192 + cw] = packh2(o[nt][2] * invb, o[nt][3] * invb);
    }
}

// ---------------- launch ----------------
extern "C" void kernel_launch(void* const* d_in, const int* in_sizes, int n_in,
                              void* d_out, int out_size) {
    const float* x        = (const float*)d_in[0];
    const float* mask     = (const float*)d_in[1];
    const float* w_qkv    = (const float*)d_in[2];
    const float* b_qkv    = (const float*)d_in[3];
    const float* w_out    = (const float*)d_in[4];
    const float* b_out    = (const float*)d_in[5];
    const float* btab     = (const float*)d_in[6];
    const int*   pos_idx  = (const int*)d_in[7];
    float* out = (float*)d_out;

    __half *xh, *qkvh, *atth;
    unsigned *wqp, *wop;
    float *bqs, *btabT, *maskL;
    unsigned short* rix;
    cudaGetSymbolAddress((void**)&xh, g_xh);
    cudaGetSymbolAddress((void**)&qkvh, g_qkvh);
    cudaGetSymbolAddress((void**)&atth, g_atth);
    cudaGetSymbolAddress((void**)&wqp, g_wqp);
    cudaGetSymbolAddress((void**)&wop, g_wop);
    cudaGetSymbolAddress((void**)&bqs, g_bqs);
    cudaGetSymbolAddress((void**)&rix, g_rix);
    cudaGetSymbolAddress((void**)&btabT, g_btabT);
    cudaGetSymbolAddress((void**)&maskL, g_maskL);

    cudaFuncSetAttribute(attn_k, cudaFuncAttributeMaxDynamicSharedMemorySize, ATT_SMEM_BYTES);
    cudaFuncSetAttribute(gemm_cp_k<true>,  cudaFuncAttributeMaxDynamicSharedMemorySize, GSM_BYTES);
    cudaFuncSetAttribute(gemm_cp_k<false>, cudaFuncAttributeMaxDynamicSharedMemorySize, GSM_BYTES);

    // preprocessing
    int n4 = (BW_ * NT_ * DIM_) / 4;
    conv_x_k<<<(n4 + 255) / 256, 256>>>(x, xh, n4);
    pack_wq_k<<<((DIM_/2) * QKVN + 255) / 256, 256>>>(w_qkv, wqp);
    pack_wo_k<<<((DIM_/2) * DIM_ + 255) / 256, 256>>>(w_out, wop);
    prep_bq_k<<<(QKVN + 255) / 256, 256>>>(b_qkv, bqs);
    prep_rix_k<<<(8 * NN_ + 255) / 256, 256>>>(pos_idx, rix);
    prep_btabT_k<<<(TOW_ * H_ * TABLE_ + 255) / 256, 256>>>(btab, btabT);
    prep_maskL_k<<<(8 * NN_ + 255) / 256, 256>>>(mask, maskL);

    // QKV projection: (36864 x 384) @ (384 x 1152) + b   -> half
    gemm_cp_k<true><<<dim3(QKVN / 128, (BW_ * NT_) / 128), 256, GSM_BYTES>>>(
        xh, wqp, bqs, qkvh, QKVN, DIM_);

    // fused attention
    attn_k<<<dim3(H_, BW_), 288, ATT_SMEM_BYTES>>>(qkvh, maskL, btabT, rix, atth);

    // output projection: (36864 x 384) @ (384 x 384) + b -> float
    gemm_cp_k<false><<<dim3(DIM_ / 128, (BW_ * NT_) / 128), 256, GSM_BYTES>>>(
        atth, wop, b_out, out, DIM_, DIM_);
}

// round 9
// speedup vs baseline: 3.5675x; 1.0460x over previous
#include <cuda_runtime.h>
#include <cuda_bf16.h>
#include <cuda_fp16.h>
#include <cstdint>

// Problem constants
#define BW_   256
#define NT_   144
#define DIM_  384
#define H_    12
#define HD_   32
#define NN_   (NT_*NT_)    // 20736
#define TOW_  32
#define TABLE_ 3312
#define QKVN  1152
#define L2E   1.4426950408889634f
#define QS_   (0.17677669529663687f * L2E)

// ---------------- scratch ----------------
__device__ __half g_xh[(size_t)BW_ * NT_ * DIM_];        // 28 MB
__device__ __half g_qkvh[(size_t)BW_ * NT_ * QKVN];      // 85 MB
__device__ __half g_atth[(size_t)BW_ * NT_ * DIM_];      // 28 MB
__device__ unsigned g_wqp[(DIM_/2) * QKVN];              // kp-paired w_qkv (q-scaled)
__device__ unsigned g_wop[(DIM_/2) * DIM_];              // kp-paired w_out
__device__ float g_bqs[QKVN];                            // scaled qkv bias
__device__ unsigned short g_rix[8 * NN_];
__device__ float g_btabT[TOW_ * H_ * TABLE_];            // [t][h][r] * log2e
__device__ float g_maskL[8 * NN_];                       // mask * log2e

// section sizes for the fused prep
#define PREP_X4   ((BW_ * NT_ * DIM_) / 4)       // 3,538,944  <- LARGEST (sets grid)
#define PREP_WQ   ((DIM_/2) * QKVN)              //   221,184
#define PREP_WO   ((DIM_/2) * DIM_)              //    73,728
#define PREP_RM   (8 * NN_)                      //   165,888
#define PREP_BT   (TOW_ * H_ * TABLE_)           // 1,271,808

// ---------------- fused prep: ONE launch, sectioned by idx ----------------
__global__ void prep_all_k(const float* __restrict__ x, const float* __restrict__ w_qkv,
                           const float* __restrict__ b_qkv, const float* __restrict__ w_out,
                           const float* __restrict__ btab, const int* __restrict__ pi,
                           const float* __restrict__ mask,
                           __half* __restrict__ xh, unsigned* __restrict__ wqp,
                           unsigned* __restrict__ wop, float* __restrict__ bqs,
                           unsigned short* __restrict__ rix, float* __restrict__ btabT,
                           float* __restrict__ maskL) {
    const int idx = blockIdx.x * 256 + threadIdx.x;
    // 1. x -> half, float4 granularity (3,538,944 items)
    if (idx < PREP_X4) {
        float4 v = *(const float4*)(x + 4 * (size_t)idx);
        __half2 a = __floats2half2_rn(v.x, v.y);
        __half2 b = __floats2half2_rn(v.z, v.w);
        *(uint2*)(xh + 4 * (size_t)idx) = make_uint2(*(unsigned*)&a, *(unsigned*)&b);
    }
    // 2. w_qkv kp-paired + q-scale folded
    if (idx < PREP_WQ) {
        int kp = idx / QKVN, n = idx - kp * QKVN;
        float s = (n < DIM_) ? QS_ : 1.0f;
        __half2 h = __floats2half2_rn(w_qkv[(size_t)(2*kp) * QKVN + n] * s,
                                      w_qkv[(size_t)(2*kp+1) * QKVN + n] * s);
        wqp[idx] = *(unsigned*)&h;
    }
    // 3. w_out kp-paired
    if (idx < PREP_WO) {
        int kp = idx / DIM_, n = idx - kp * DIM_;
        __half2 h = __floats2half2_rn(w_out[(size_t)(2*kp) * DIM_ + n],
                                      w_out[(size_t)(2*kp+1) * DIM_ + n]);
        wop[idx] = *(unsigned*)&h;
    }
    // 4. scaled qkv bias
    if (idx < QKVN) bqs[idx] = b_qkv[idx] * ((idx < DIM_) ? QS_ : 1.0f);
    // 5. rix + scaled mask
    if (idx < PREP_RM) {
        int gw = idx / NN_, ij = idx - gw * NN_;
        rix[idx] = (unsigned short)pi[(ij * 8 + gw) % NN_];
        maskL[idx] = mask[idx] * L2E;
    }
    // 6. bias table transpose+scale
    if (idx < PREP_BT) {
        int th = idx / TABLE_, r = idx - th * TABLE_;
        int t = th / H_, h = th - t * H_;
        btabT[idx] = btab[(r * TOW_ + t) * H_ + h] * L2E;
    }
}

// ---------------- math helpers ----------------
__device__ __forceinline__ float ex2f(float x) {
    float r; asm("ex2.approx.ftz.f32 %0, %1;" : "=f"(r) : "f"(x)); return r;
}
__device__ __forceinline__ unsigned packh2(float a, float b) {
    __half2 h = __floats2half2_rn(a, b);
    return *reinterpret_cast<unsigned*>(&h);
}
__device__ __forceinline__ void mma_f16(float d[4], unsigned a0, unsigned a1,
                                        unsigned a2, unsigned a3,
                                        unsigned b0, unsigned b1) {
    asm volatile(
        "mma.sync.aligned.m16n8k16.row.col.f32.f16.f16.f32 "
        "{%0,%1,%2,%3},{%4,%5,%6,%7},{%8,%9},{%0,%1,%2,%3};"
        : "+f"(d[0]), "+f"(d[1]), "+f"(d[2]), "+f"(d[3])
        : "r"(a0), "r"(a1), "r"(a2), "r"(a3), "r"(b0), "r"(b1));
}
__device__ __forceinline__ void cpa16(unsigned dst, const void* src) {
    asm volatile("cp.async.cg.shared.global [%0], [%1], 16;" :: "r"(dst), "l"(src));
}
#define CPA_COMMIT() asm volatile("cp.async.commit_group;")
#define CPA_WAIT1()  asm volatile("cp.async.wait_group 1;")
#define CPA_WAIT0()  asm volatile("cp.async.wait_group 0;")

// ---------------- GEMM: C = A(half,[M][K]) @ W(kp-paired u32,[K/2][N]) + bias ----
// Tile 128x128, KC=64, 256 threads, 3-stage cp.async pipeline. (R6, tail-fixed)
#define GSM_BYTES (3 * (16384 + 16384))
template<bool HALF_OUT>
__global__ void __launch_bounds__(256, 2)
gemm_cp_k(const __half* __restrict__ A, const unsigned* __restrict__ Bp,
          const float* __restrict__ bias, void* __restrict__ Cv,
          int N, int K) {
    extern __shared__ unsigned smg[];
    unsigned* As = smg;              // [3][4096]
    unsigned* Bs = smg + 3 * 4096;   // [3][4096]
    const unsigned sa_base = (unsigned)__cvta_generic_to_shared(As);
    const unsigned sb_base = (unsigned)__cvta_generic_to_shared(Bs);

    const int tid  = threadIdx.x;
    const int lane = tid & 31;
    const int warp = tid >> 5;
    const int wm = (warp >> 1) * 32;
    const int wn = (warp & 1) * 64;
    const int g = lane >> 2;
    const int t = lane & 3;

    const int m0 = blockIdx.y * 128;
    const int n0 = blockIdx.x * 128;
    const int nch = K / 64;

    float acc[2][8][4];
#pragma unroll
    for (int mt = 0; mt < 2; mt++)
#pragma unroll
        for (int nt = 0; nt < 8; nt++)
#pragma unroll
            for (int i = 0; i < 4; i++) acc[mt][nt][i] = 0.f;

    int bcol[8];
#pragma unroll
    for (int nt = 0; nt < 8; nt++) bcol[nt] = ((wn + nt * 8) ^ (t << 3)) + g;

#define GEMM_ISSUE(stage, ch) do {                                              \
        int kc_ = (ch) * 64;                                                    \
        unsigned ab_ = sa_base + (stage) * 16384;                               \
        unsigned bb_ = sb_base + (stage) * 16384;                               \
        _Pragma("unroll")                                                       \
        for (int p = 0; p < 4; p++) {                                           \
            int idx = tid + p * 256;                                            \
            int r = idx >> 3, g4 = idx & 7;                                     \
            unsigned dst = ab_ + (r * 32 + 4 * (g4 ^ (r & 7))) * 4;             \
            cpa16(dst, A + (size_t)(m0 + r) * K + kc_ + g4 * 8);                \
        }                                                                       \
        _Pragma("unroll")                                                       \
        for (int p = 0; p < 4; p++) {                                           \
            int idx = tid + p * 256;                                            \
            int kp = idx >> 5, g4 = idx & 31;                                   \
            unsigned dst = bb_ + (kp * 128 + 4 * (g4 ^ (2 * (kp & 3)))) * 4;    \
            cpa16(dst, Bp + (size_t)(kc_ / 2 + kp) * N + n0 + g4 * 4);          \
        }                                                                       \
    } while (0)

    GEMM_ISSUE(0, 0); CPA_COMMIT();
    GEMM_ISSUE(1, 1); CPA_COMMIT();

    for (int it = 0; it < nch; it++) {
        if (it + 1 == nch) { CPA_WAIT0(); } else { CPA_WAIT1(); }
        __syncthreads();
        if (it + 2 < nch) { GEMM_ISSUE((it + 2) % 3, it + 2); CPA_COMMIT(); }

        const unsigned* as = As + (it % 3) * 4096;
        const unsigned* bs = Bs + (it % 3) * 4096;
#pragma unroll
        for (int ks = 0; ks < 4; ks++) {
            const int w0 = (8 * ks + t) ^ (g << 2);
            const int w1 = (8 * ks + 4 + t) ^ (g << 2);
            unsigned af[2][4];
#pragma unroll
            for (int mt = 0; mt < 2; mt++) {
                const unsigned* ra = as + (wm + mt * 16 + g) * 32;
                af[mt][0] = ra[w0];
                af[mt][1] = ra[8 * 32 + w0];
                af[mt][2] = ra[w1];
                af[mt][3] = ra[8 * 32 + w1];
            }
            const unsigned* b0r = bs + (8 * ks + t) * 128;
            const unsigned* b1r = bs + (8 * ks + 4 + t) * 128;
#pragma unroll
            for (int nt = 0; nt < 8; nt++) {
                unsigned b0 = b0r[bcol[nt]];
                unsigned b1 = b1r[bcol[nt]];
#pragma unroll
                for (int mt = 0; mt < 2; mt++)
                    mma_f16(acc[mt][nt], af[mt][0], af[mt][1], af[mt][2], af[mt][3], b0, b1);
            }
        }
    }

#pragma unroll
    for (int mt = 0; mt < 2; mt++) {
#pragma unroll
        for (int nt = 0; nt < 8; nt++) {
            int row = m0 + wm + mt * 16 + g;
            int col = n0 + wn + nt * 8 + (t << 1);
            float b0 = __ldg(bias + col);
            float b1 = __ldg(bias + col + 1);
            float v0 = acc[mt][nt][0] + b0, v1 = acc[mt][nt][1] + b1;
            float v2 = acc[mt][nt][2] + b0, v3 = acc[mt][nt][3] + b1;
            if (HALF_OUT) {
                unsigned* C = (unsigned*)Cv;
                C[(size_t)row * (N >> 1) + (col >> 1)] = packh2(v0, v1);
                C[(size_t)(row + 8) * (N >> 1) + (col >> 1)] = packh2(v2, v3);
            } else {
                float* C = (float*)Cv;
                *(float2*)(C + (size_t)row * N + col) = make_float2(v0, v1);
                *(float2*)(C + (size_t)(row + 8) * N + col) = make_float2(v2, v3);
            }
        }
    }
#undef GEMM_ISSUE
}

// ---------------- fused attention: one CTA per (head, window) ----------------
// smem (u32): qh[144*36] | kh[144*36] | vh[72*40] | tcol[3312]
#define QK_STR 36
#define ATT_SMEM_WORDS (5184 + 5184 + 2880 + 3312)
#define ATT_SMEM_BYTES (ATT_SMEM_WORDS * 4)

__global__ void __launch_bounds__(288, 2)
attn_k(const __half* __restrict__ qkvh, const float* __restrict__ maskL,
       const float* __restrict__ btabT, const unsigned short* __restrict__ rix,
       __half* __restrict__ atth) {
    extern __shared__ unsigned sm[];
    unsigned* qh = sm;                       // [144][36]
    unsigned* kh = sm + 5184;                // [144][36]
    unsigned* vh = sm + 10368;               // [72][40]
    float*  tcol = (float*)(sm + 13248);     // [3312]

    const int h   = blockIdx.x;
    const int bw  = blockIdx.y;
    const int tid = threadIdx.x;
    const int lane = tid & 31;
    const int warp = tid >> 5;               // 0..8
    const int g  = lane >> 2;
    const int tq = lane & 3;
    const int r0 = warp * 16;

    const int ti = bw & 31;
    const int gw = bw >> 5;
    const int w  = bw & 7;

    const unsigned* bu = (const unsigned*)qkvh + (size_t)bw * NT_ * 576 + h * 16;

    // ---- stage q,k (pure copies; q pre-scaled in weights) ----
    for (int idx = tid; idx < 576; idx += 288) {
        int n = idx >> 2, s = (idx & 3) << 2;
        const unsigned* p = bu + (size_t)n * 576 + s;
        *(uint4*)(qh + n * QK_STR + s) = *(const uint4*)p;
        *(uint4*)(kh + n * QK_STR + s) = *(const uint4*)(p + 192);
    }
    // ---- stage V paired along tokens ----
    for (int idx = tid; idx < 576; idx += 288) {
        int jp = idx >> 3, s = idx & 7;
        const unsigned* p0 = bu + (size_t)(2 * jp) * 576 + 384 + s * 2;
        uint2 u = *(const uint2*)p0;
        uint2 v = *(const uint2*)(p0 + 576);
        uint4 o;
        o.x = __byte_perm(u.x, v.x, 0x5410);
        o.y = __byte_perm(u.x, v.x, 0x7632);
        o.z = __byte_perm(u.y, v.y, 0x5410);
        o.w = __byte_perm(u.y, v.y, 0x7632);
        *(uint4*)(vh + jp * 40 + s * 4) = o;
    }
    // ---- stage bias column ----
    {
        const float* bt = btabT + (size_t)(ti * H_ + h) * TABLE_;
        for (int r = tid; r < TABLE_; r += 288) tcol[r] = bt[r];
    }
    __syncthreads();

    // ---- per-nt interleaved: S-tile MMA -> bias/mask gather -> exp -> pack ----
    unsigned aq[2][4];
#pragma unroll
    for (int ks = 0; ks < 2; ks++) {
        aq[ks][0] = qh[(r0 + g) * QK_STR + ks * 8 + tq];
        aq[ks][1] = qh[(r0 + g + 8) * QK_STR + ks * 8 + tq];
        aq[ks][2] = qh[(r0 + g) * QK_STR + ks * 8 + tq + 4];
        aq[ks][3] = qh[(r0 + g + 8) * QK_STR + ks * 8 + tq + 4];
    }

    const int ia = r0 + g, ib = r0 + g + 8;
    const unsigned short* rra = rix + gw * NN_ + ia * NT_;
    const unsigned short* rrb = rix + gw * NN_ + ib * NT_;
    const float* mra = maskL + w * NN_ + ia * NT_;
    const float* mrb = maskL + w * NN_ + ib * NT_;

    float sa = 0.f, sb = 0.f;
    uint2 pf[18];
#pragma unroll
    for (int nt = 0; nt < 18; nt++) {
        float acc4[4] = {0.f, 0.f, 0.f, 0.f};
#pragma unroll
        for (int ks = 0; ks < 2; ks++) {
            unsigned b0 = kh[(nt * 8 + g) * QK_STR + ks * 8 + tq];
            unsigned b1 = kh[(nt * 8 + g) * QK_STR + ks * 8 + tq + 4];
            mma_f16(acc4, aq[ks][0], aq[ks][1], aq[ks][2], aq[ks][3], b0, b1);
        }
        int j = nt * 8 + 2 * tq;
        unsigned ra = *(const unsigned*)(rra + j);
        unsigned rb = *(const unsigned*)(rrb + j);
        float2 ma = *(const float2*)(mra + j);
        float2 mb = *(const float2*)(mrb + j);
        float y0 = acc4[0] + tcol[ra & 0xFFFF] + ma.x;
        float y1 = acc4[1] + tcol[ra >> 16]    + ma.y;
        float y2 = acc4[2] + tcol[rb & 0xFFFF] + mb.x;
        float y3 = acc4[3] + tcol[rb >> 16]    + mb.y;
        float e0 = ex2f(y0), e1 = ex2f(y1), e2 = ex2f(y2), e3 = ex2f(y3);
        sa += e0 + e1;
        sb += e2 + e3;
        pf[nt].x = packh2(e0, e1);
        pf[nt].y = packh2(e2, e3);
    }
    sa += __shfl_xor_sync(0xffffffffu, sa, 1);
    sa += __shfl_xor_sync(0xffffffffu, sa, 2);
    sb += __shfl_xor_sync(0xffffffffu, sb, 1);
    sb += __shfl_xor_sync(0xffffffffu, sb, 2);
    const float inva = 1.0f / sa;
    const float invb = 1.0f / sb;

    // ---- O = P @ V (A fragments straight from pf registers) ----
    float o[4][4];
#pragma unroll
    for (int nt = 0; nt < 4; nt++)
#pragma unroll
        for (int i = 0; i < 4; i++) o[nt][i] = 0.f;

#pragma unroll
    for (int kt = 0; kt < 9; kt++) {
        unsigned a0 = pf[2 * kt].x;
        unsigned a1 = pf[2 * kt].y;
        unsigned a2 = pf[2 * kt + 1].x;
        unsigned a3 = pf[2 * kt + 1].y;
#pragma unroll
        for (int nt = 0; nt < 4; nt++) {
            unsigned b0 = vh[(8 * kt + tq) * 40 + nt * 8 + g];
            unsigned b1 = vh[(8 * kt + tq + 4) * 40 + nt * 8 + g];
            mma_f16(o[nt], a0, a1, a2, a3, b0, b1);
        }
    }

    // ---- normalize + store half ----
    unsigned* orow = (unsigned*)atth + (size_t)bw * NT_ * 192 + h * 16;
#pragma unroll
    for (int nt = 0; nt < 4; nt++) {
        int cw = nt * 4 + tq;
        orow[(size_t)ia * 192 + cw] = packh2(o[nt][0] * inva, o[nt][1] * inva);
        orow[(size_t)ib * 192 + cw] = packh2(o[nt][2] * invb, o[nt][3] * invb);
    }
}

// ---------------- launch ----------------
extern "C" void kernel_launch(void* const* d_in, const int* in_sizes, int n_in,
                              void* d_out, int out_size) {
    const float* x        = (const float*)d_in[0];
    const float* mask     = (const float*)d_in[1];
    const float* w_qkv    = (const float*)d_in[2];
    const float* b_qkv    = (const float*)d_in[3];
    const float* w_out    = (const float*)d_in[4];
    const float* b_out    = (const float*)d_in[5];
    const float* btab     = (const float*)d_in[6];
    const int*   pos_idx  = (const int*)d_in[7];
    float* out = (float*)d_out;

    __half *xh, *qkvh, *atth;
    unsigned *wqp, *wop;
    float *bqs, *btabT, *maskL;
    unsigned short* rix;
    cudaGetSymbolAddress((void**)&xh, g_xh);
    cudaGetSymbolAddress((void**)&qkvh, g_qkvh);
    cudaGetSymbolAddress((void**)&atth, g_atth);
    cudaGetSymbolAddress((void**)&wqp, g_wqp);
    cudaGetSymbolAddress((void**)&wop, g_wop);
    cudaGetSymbolAddress((void**)&bqs, g_bqs);
    cudaGetSymbolAddress((void**)&rix, g_rix);
    cudaGetSymbolAddress((void**)&btabT, g_btabT);
    cudaGetSymbolAddress((void**)&maskL, g_maskL);

    cudaFuncSetAttribute(attn_k, cudaFuncAttributeMaxDynamicSharedMemorySize, ATT_SMEM_BYTES);
    cudaFuncSetAttribute(gemm_cp_k<true>,  cudaFuncAttributeMaxDynamicSharedMemorySize, GSM_BYTES);
    cudaFuncSetAttribute(gemm_cp_k<false>, cudaFuncAttributeMaxDynamicSharedMemorySize, GSM_BYTES);

    // fused preprocessing — grid sized by the LARGEST section (x-conversion: 3,538,944)
    prep_all_k<<<(PREP_X4 + 255) / 256, 256>>>(
        x, w_qkv, b_qkv, w_out, btab, pos_idx, mask,
        xh, wqp, wop, bqs, rix, btabT, maskL);

    // QKV projection: (36864 x 384) @ (384 x 1152) + b -> half
    gemm_cp_k<true><<<dim3(QKVN / 128, (BW_ * NT_) / 128), 256, GSM_BYTES>>>(
        xh, wqp, bqs, qkvh, QKVN, DIM_);

    // fused attention
    attn_k<<<dim3(H_, BW_), 288, ATT_SMEM_BYTES>>>(qkvh, maskL, btabT, rix, atth);

    // output projection: (36864 x 384) @ (384 x 384) + b -> float
    gemm_cp_k<false><<<dim3(DIM_ / 128, (BW_ * NT_) / 128), 256, GSM_BYTES>>>(
        atth, wop, b_out, out, DIM_, DIM_);
}